// round 14
// baseline (speedup 1.0000x reference)
#include <cuda_runtime.h>
#include <float.h>

#define D      8192
#define D4     2048          // D / 4 (float4 per row)
#define GAMMA  0.95f
#define NSLAB  64            // row slabs in kernel 1
#define RSLAB  128           // rows per slab (NSLAB * RSLAB = D)
#define NBLK1  513           // 512 colred blocks + 1 scalar block

// ---------------- device scratch (no allocations allowed) ----------------
__device__ float g_part_dot[NSLAB][D];   // fully rewritten every call
__device__ float g_part_sq [NSLAB][D];
__device__ float g_evsum[64];            // per-block partial sums of ev
__device__ float g_minpart[64];          // per-block partial mins of w_u_new
__device__ float g_knorm;                // ||k||
__device__ float g_wr  [D];              // w_r with column min_idx zeroed
__device__ float g_addk[D];              // w_u_new * k (per column add for mk)
__device__ float g_addu[D];              // w_w_new * u (per column add for mu)
__device__ int   g_min_idx;
// device-side barrier state (self-resetting -> graph-replay safe)
__device__ unsigned g_arr1;              // arrivals of all 513 blocks
__device__ unsigned g_arr2;              // arrivals of the 64 epilogue blocks
__device__ unsigned g_dep;               // departures of the 64 epilogue blocks

// output layout (element offsets into d_out, float32)
#define OFF_UF  ((size_t)0)
#define OFF_MK  ((size_t)D)
#define OFF_MU  ((size_t)D + (size_t)D * D)
#define OFF_WW  ((size_t)D + 2ull * (size_t)D * D)
#define OFF_WU  (OFF_WW + (size_t)D)
#define OFF_WLU (OFF_WU + (size_t)D)

// ---------------- warp helpers ----------------
__device__ __forceinline__ float warp_sum(float v) {
#pragma unroll
    for (int o = 16; o > 0; o >>= 1) v += __shfl_xor_sync(0xffffffffu, v, o);
    return v;
}
__device__ __forceinline__ float warp_min(float v) {
#pragma unroll
    for (int o = 16; o > 0; o >>= 1) v = fminf(v, __shfl_xor_sync(0xffffffffu, v, o));
    return v;
}

// ---------------- kernel 1 FUSED: colred + k0 + simexp + vector epilogue ----
// grid 513 x 256, all blocks co-resident (capacity 592 at 4 blocks/SM).
// EXACT Round-12 bodies; only addition: early PDL trigger after each block's
// barrier arrive, so the secondary is scheduled during the epilogue tail.
__global__ void __launch_bounds__(256, 4)
k1_fused(const float* __restrict__ mk,
         const float* __restrict__ kvec,
         const float* __restrict__ w_u,
         const float* __restrict__ uvec,
         const float* __restrict__ w_w,
         const float* __restrict__ w_lu,
         const float* __restrict__ beta_p,
         float* __restrict__ out)
{
    const int bid  = blockIdx.x;
    const int tid  = threadIdx.x;
    const int lane = tid & 31;
    const int wid  = tid >> 5;

    if (bid == 512) {
        // ---- scalar block: ||k||^2 and first-index argmin(w_u) ----
        __shared__ float sredf[8];
        __shared__ int   sredi[8];

        float ks = 0.f;
        float bestv = FLT_MAX;
        int   besti = 0x7fffffff;
#pragma unroll 8
        for (int p = 0; p < 32; ++p) {
            int j = tid + p * 256;
            float kj = kvec[j];
            ks += kj * kj;
            float wuj = w_u[j];
            if (wuj < bestv || (wuj == bestv && j < besti)) { bestv = wuj; besti = j; }
        }
        {
            float v = warp_sum(ks);
            if (lane == 0) sredf[wid] = v;
            __syncthreads();
            if (tid == 0) {
                float t = 0.f;
#pragma unroll
                for (int w = 0; w < 8; ++w) t += sredf[w];
                g_knorm = sqrtf(t);
            }
            __syncthreads();
        }
        {
#pragma unroll
            for (int o = 16; o > 0; o >>= 1) {
                float ov = __shfl_xor_sync(0xffffffffu, bestv, o);
                int   oi = __shfl_xor_sync(0xffffffffu, besti, o);
                if (ov < bestv || (ov == bestv && oi < besti)) { bestv = ov; besti = oi; }
            }
            if (lane == 0) { sredf[wid] = bestv; sredi[wid] = besti; }
            __syncthreads();
            if (tid == 0) {
                float bv = sredf[0]; int bi = sredi[0];
#pragma unroll
                for (int w = 1; w < 8; ++w) {
                    if (sredf[w] < bv || (sredf[w] == bv && sredi[w] < bi)) {
                        bv = sredf[w]; bi = sredi[w];
                    }
                }
                g_min_idx = bi;
            }
        }
        __syncthreads();
        __threadfence();
        if (tid == 0) atomicAdd(&g_arr1, 1u);
#if __CUDA_ARCH__ >= 900
        cudaTriggerProgrammaticLaunchCompletion();
#endif
        return;
    }

    // ---- Round-3 colred body (FROZEN) ----
    {
        __shared__ float sk[RSLAB];
        const int ct  = bid & 7;
        const int rs  = bid >> 3;
        const int row0 = rs * RSLAB;

        if (tid < RSLAB) sk[tid] = kvec[row0 + tid];
        __syncthreads();

        const int col4 = ct * 256 + tid;
        const float4* __restrict__ mk4 = (const float4*)mk + (size_t)row0 * D4 + col4;

        float4 ad = make_float4(0.f, 0.f, 0.f, 0.f);
        float4 as = make_float4(0.f, 0.f, 0.f, 0.f);

        for (int r = 0; r < RSLAB; r += 8) {
            float4 v[8];
#pragma unroll
            for (int i = 0; i < 8; ++i)
                v[i] = __ldcs(mk4 + (size_t)(r + i) * D4);
#pragma unroll
            for (int i = 0; i < 8; ++i) {
                float kr = sk[r + i];
                ad.x += kr * v[i].x; ad.y += kr * v[i].y;
                ad.z += kr * v[i].z; ad.w += kr * v[i].w;
                as.x += v[i].x * v[i].x; as.y += v[i].y * v[i].y;
                as.z += v[i].z * v[i].z; as.w += v[i].w * v[i].w;
            }
        }

        ((float4*)g_part_dot[rs])[col4] = ad;
        ((float4*)g_part_sq [rs])[col4] = as;
    }

    __syncthreads();
    __threadfence();
    if (tid == 0) atomicAdd(&g_arr1, 1u);
#if __CUDA_ARCH__ >= 900
    cudaTriggerProgrammaticLaunchCompletion();
#endif

    if (bid >= 64) return;   // colred-only blocks are done

    // ================= epilogue blocks 0..63 =================
    if (tid == 0) {
        while (atomicAdd(&g_arr1, 0u) < (unsigned)NBLK1) __nanosleep(64);
    }
    __syncthreads();
    __threadfence();

    __shared__ float sred[4];
    __shared__ float s_sum;
    __shared__ float shalf_d[128];
    __shared__ float shalf_s[128];

    // ---- slab reduction with 256 threads (two half-slab partials per j) ----
    const int jl   = tid & 127;
    const int half = tid >> 7;
    const int j    = bid * 128 + jl;
    {
        float sd = 0.f, ss = 0.f;
        const int s0 = half * 32;
#pragma unroll
        for (int s = 0; s < 32; ++s) {
            sd += g_part_dot[s0 + s][j];
            ss += g_part_sq [s0 + s][j];
        }
        if (half == 1) { shalf_d[jl] = sd; shalf_s[jl] = ss; }
        __syncthreads();
        if (half == 0) { shalf_d[jl] += sd; shalf_s[jl] += ss; }
    }
    __syncthreads();

    float ev = 0.f;
    if (tid < 128) {
        const float sd = shalf_d[jl];
        const float ss = shalf_s[jl];
        ev = __expf(sd / (g_knorm * sqrtf(ss)));
        float v = warp_sum(ev);
        if (lane == 0) sred[wid] = v;
    }
    __syncthreads();
    if (tid == 0) {
        g_evsum[bid] = (sred[0] + sred[1]) + (sred[2] + sred[3]);
        __threadfence();
        atomicAdd(&g_arr2, 1u);
    }

    if (tid == 0) {
        while (atomicAdd(&g_arr2, 0u) < 64u) __nanosleep(64);
    }
    __syncthreads();
    __threadfence();

    // ---- softmax denominator (same deterministic order as R9-R13) ----
    if (tid < 32) {
        float t = g_evsum[tid] + g_evsum[tid + 32];
        t = warp_sum(t);
        if (tid == 0) s_sum = t;
    }
    __syncthreads();

    const float inv_sum = 1.f / s_sum;
    const float beta    = 1.f / (1.f + __expf(-beta_p[0]));
    const int   minidx  = g_min_idx;

    if (tid < 128) {
        const float wr     = ev * inv_sum;
        const float wu_new = GAMMA * w_u[j] + wr + w_w[j];
        const float ww_new = beta * wr + (1.f - beta) * w_lu[j];

        out[OFF_WU + j] = wu_new;
        out[OFF_WW + j] = ww_new;
        g_addk[j] = wu_new * kvec[j];
        g_addu[j] = ww_new * uvec[j];
        g_wr[j]   = (j == minidx) ? 0.f : wr;

        float v = warp_min(wu_new);
        if (lane == 0) sred[wid] = v;
    }
    __syncthreads();
    if (tid == 0) {
        g_minpart[bid] = fminf(fminf(sred[0], sred[1]), fminf(sred[2], sred[3]));
        __threadfence();
        unsigned d = atomicAdd(&g_dep, 1u);
        if (d == 63u) {
            atomicExch(&g_arr1, 0u);
            atomicExch(&g_arr2, 0u);
            atomicExch(&g_dep,  0u);
        }
    }
}

// ---------------- kernel 3+4 fused + w_lu finisher (PDL secondary) ----------
// NEW: before gridsync, each block L2-prefetches the first 8KB of each of its
// 8 src rows (mk/mu are NOT written by k1_fused -> pre-sync reads are legal).
// First-wave prefetch total ~74MB < L2. Body after the sync is byte-identical
// to the frozen Round-12 version.
__global__ __launch_bounds__(256) void k34_stream(const float* __restrict__ mk,
                                                  const float* __restrict__ mu,
                                                  float* __restrict__ out)
{
    const int tid  = threadIdx.x;
    const int lane = tid & 31;
    const int wid  = tid >> 5;

#if __CUDA_ARCH__ >= 900
    if (blockIdx.x != 2048) {
        const char* rowbase;
        if (blockIdx.x < 1024)
            rowbase = (const char*)mk + ((size_t)blockIdx.x * 8 + wid) * D * 4;
        else
            rowbase = (const char*)mu + ((size_t)(blockIdx.x - 1024) * 8 + wid) * D * 4;
        // 64 lines x 128B = 8KB per row, 2 lines per lane
#pragma unroll
        for (int i = 0; i < 2; ++i)
            asm volatile("prefetch.global.L2 [%0];"
                         :: "l"(rowbase + (size_t)(lane + i * 32) * 128));
    }
    cudaGridDependencySynchronize();
#endif

    if (blockIdx.x == 2048) {
        // ---- w_lu_new finisher ----
        __shared__ float s_min;
        if (tid < 32) {
            float t = fminf(g_minpart[tid], g_minpart[tid + 32]);
            t = warp_min(t);
            if (tid == 0) s_min = t;
        }
        __syncthreads();
        const float minv = s_min;
#pragma unroll 8
        for (int p = 0; p < 32; ++p) {
            int j = tid + p * 256;
            out[OFF_WLU + j] = (out[OFF_WU + j] < minv) ? 1.f : 0.f;
        }
        return;
    }

    const int m   = g_min_idx;
    const int m4  = m >> 2;
    const int ml  = m & 3;

    if (blockIdx.x < 1024) {
        // ---------------- mk path ----------------
        const int row = blockIdx.x * 8 + wid;
        const float4* __restrict__ src = (const float4*)mk + (size_t)row * D4;
        float4* __restrict__ dst = (float4*)(out + OFF_MK) + (size_t)row * D4;
        const float4* __restrict__ wr4 = (const float4*)g_wr;
        const float4* __restrict__ ak4 = (const float4*)g_addk;

        float acc = 0.f;
#pragma unroll 8
        for (int it = 0; it < 64; ++it) {
            const int f = lane + (it << 5);
            float4 v = src[f];
            float4 w = __ldg(wr4 + f);
            float4 a = __ldg(ak4 + f);
            acc += w.x * v.x + w.y * v.y + w.z * v.z + w.w * v.w;
            float4 o = make_float4(v.x + a.x, v.y + a.y, v.z + a.z, v.w + a.w);
            if (f == m4) {
                if      (ml == 0) o.x = a.x;
                else if (ml == 1) o.y = a.y;
                else if (ml == 2) o.z = a.z;
                else              o.w = a.w;
            }
            dst[f] = o;
        }
        acc = warp_sum(acc);
        if (lane == 0) out[OFF_UF + row] = acc;
    } else {
        // ---------------- mu path ----------------
        const int row = (blockIdx.x - 1024) * 8 + wid;
        const float4* __restrict__ src = (const float4*)mu + (size_t)row * D4;
        float4* __restrict__ dst = (float4*)(out + OFF_MU) + (size_t)row * D4;
        const float4* __restrict__ au4 = (const float4*)g_addu;

#pragma unroll 8
        for (int it = 0; it < 64; ++it) {
            const int f = lane + (it << 5);
            float4 v = src[f];
            float4 a = __ldg(au4 + f);
            float4 o = make_float4(v.x + a.x, v.y + a.y, v.z + a.z, v.w + a.w);
            if (f == m4) {
                if      (ml == 0) o.x = a.x;
                else if (ml == 1) o.y = a.y;
                else if (ml == 2) o.z = a.z;
                else              o.w = a.w;
            }
            dst[f] = o;
        }
    }
}

// ---------------- launch ----------------
extern "C" void kernel_launch(void* const* d_in, const int* in_sizes, int n_in,
                              void* d_out, int out_size)
{
    const float* k_in   = (const float*)d_in[0];
    const float* u_in   = (const float*)d_in[1];
    const float* mk_in  = (const float*)d_in[2];
    const float* mu_in  = (const float*)d_in[3];
    const float* ww_in  = (const float*)d_in[4];
    const float* wu_in  = (const float*)d_in[5];
    const float* wlu_in = (const float*)d_in[6];
    const float* beta_in= (const float*)d_in[7];
    float* out = (float*)d_out;

    k1_fused<<<NBLK1, 256>>>(mk_in, k_in, wu_in, u_in, ww_in, wlu_in, beta_in, out);

    // PDL launch of k34: scheduled at the early trigger; pre-sync prefetch
    // warms L2 during k1's epilogue tail; gridsync gates data consumption.
    cudaLaunchConfig_t cfg = {};
    cfg.gridDim  = dim3(2049, 1, 1);
    cfg.blockDim = dim3(256, 1, 1);
    cfg.dynamicSmemBytes = 0;
    cfg.stream = 0;
    cudaLaunchAttribute attrs[1];
    attrs[0].id = cudaLaunchAttributeProgrammaticStreamSerialization;
    attrs[0].val.programmaticStreamSerializationAllowed = 1;
    cfg.attrs = attrs;
    cfg.numAttrs = 1;
    cudaLaunchKernelEx(&cfg, k34_stream, mk_in, mu_in, out);
}

// round 15
// speedup vs baseline: 1.0354x; 1.0354x over previous
#include <cuda_runtime.h>
#include <float.h>

#define D      8192
#define D4     2048          // D / 4 (float4 per row)
#define GAMMA  0.95f
#define NSLAB  64            // row slabs in kernel 1
#define RSLAB  128           // rows per slab (NSLAB * RSLAB = D)
#define NBLK1  513           // 512 colred blocks + 1 scalar block

// ---------------- device scratch (no allocations allowed) ----------------
__device__ float g_part_dot[NSLAB][D];   // fully rewritten every call
__device__ float g_part_sq [NSLAB][D];
__device__ float g_evsum[64];            // per-block partial sums of ev
__device__ float g_minpart[64];          // per-block partial mins of w_u_new
__device__ float g_knorm;                // ||k||
__device__ float g_wr  [D];              // w_r with column min_idx zeroed
__device__ float g_addk[D];              // w_u_new * k (per column add for mk)
__device__ float g_addu[D];              // w_w_new * u (per column add for mu)
__device__ int   g_min_idx;
// device-side barrier state (self-resetting -> graph-replay safe)
__device__ unsigned g_arr1;              // arrivals of all 513 blocks
__device__ unsigned g_arr2;              // arrivals of the 64 epilogue blocks
__device__ unsigned g_dep;               // departures of the 64 epilogue blocks

// output layout (element offsets into d_out, float32)
#define OFF_UF  ((size_t)0)
#define OFF_MK  ((size_t)D)
#define OFF_MU  ((size_t)D + (size_t)D * D)
#define OFF_WW  ((size_t)D + 2ull * (size_t)D * D)
#define OFF_WU  (OFF_WW + (size_t)D)
#define OFF_WLU (OFF_WU + (size_t)D)

// ---------------- warp helpers ----------------
__device__ __forceinline__ float warp_sum(float v) {
#pragma unroll
    for (int o = 16; o > 0; o >>= 1) v += __shfl_xor_sync(0xffffffffu, v, o);
    return v;
}
__device__ __forceinline__ float warp_min(float v) {
#pragma unroll
    for (int o = 16; o > 0; o >>= 1) v = fminf(v, __shfl_xor_sync(0xffffffffu, v, o));
    return v;
}

// ---------------- kernel 1 FUSED: colred + k0 + simexp + vector epilogue ----
// grid 513 x 256, all blocks co-resident (capacity 592 at 4 blocks/SM).
// EXACT Round-12/13 bodies (FROZEN); early PDL trigger after each block's
// barrier arrive (kept from R14 — zero-bandwidth, lets the secondary be
// scheduled during the epilogue tail). NO prefetch (R14's regression).
__global__ void __launch_bounds__(256, 4)
k1_fused(const float* __restrict__ mk,
         const float* __restrict__ kvec,
         const float* __restrict__ w_u,
         const float* __restrict__ uvec,
         const float* __restrict__ w_w,
         const float* __restrict__ w_lu,
         const float* __restrict__ beta_p,
         float* __restrict__ out)
{
    const int bid  = blockIdx.x;
    const int tid  = threadIdx.x;
    const int lane = tid & 31;
    const int wid  = tid >> 5;

    if (bid == 512) {
        // ---- scalar block: ||k||^2 and first-index argmin(w_u) ----
        __shared__ float sredf[8];
        __shared__ int   sredi[8];

        float ks = 0.f;
        float bestv = FLT_MAX;
        int   besti = 0x7fffffff;
#pragma unroll 8
        for (int p = 0; p < 32; ++p) {
            int j = tid + p * 256;
            float kj = kvec[j];
            ks += kj * kj;
            float wuj = w_u[j];
            if (wuj < bestv || (wuj == bestv && j < besti)) { bestv = wuj; besti = j; }
        }
        {
            float v = warp_sum(ks);
            if (lane == 0) sredf[wid] = v;
            __syncthreads();
            if (tid == 0) {
                float t = 0.f;
#pragma unroll
                for (int w = 0; w < 8; ++w) t += sredf[w];
                g_knorm = sqrtf(t);
            }
            __syncthreads();
        }
        {
#pragma unroll
            for (int o = 16; o > 0; o >>= 1) {
                float ov = __shfl_xor_sync(0xffffffffu, bestv, o);
                int   oi = __shfl_xor_sync(0xffffffffu, besti, o);
                if (ov < bestv || (ov == bestv && oi < besti)) { bestv = ov; besti = oi; }
            }
            if (lane == 0) { sredf[wid] = bestv; sredi[wid] = besti; }
            __syncthreads();
            if (tid == 0) {
                float bv = sredf[0]; int bi = sredi[0];
#pragma unroll
                for (int w = 1; w < 8; ++w) {
                    if (sredf[w] < bv || (sredf[w] == bv && sredi[w] < bi)) {
                        bv = sredf[w]; bi = sredi[w];
                    }
                }
                g_min_idx = bi;
            }
        }
        __syncthreads();
        __threadfence();
        if (tid == 0) atomicAdd(&g_arr1, 1u);
#if __CUDA_ARCH__ >= 900
        cudaTriggerProgrammaticLaunchCompletion();
#endif
        return;
    }

    // ---- Round-3 colred body (FROZEN) ----
    {
        __shared__ float sk[RSLAB];
        const int ct  = bid & 7;
        const int rs  = bid >> 3;
        const int row0 = rs * RSLAB;

        if (tid < RSLAB) sk[tid] = kvec[row0 + tid];
        __syncthreads();

        const int col4 = ct * 256 + tid;
        const float4* __restrict__ mk4 = (const float4*)mk + (size_t)row0 * D4 + col4;

        float4 ad = make_float4(0.f, 0.f, 0.f, 0.f);
        float4 as = make_float4(0.f, 0.f, 0.f, 0.f);

        for (int r = 0; r < RSLAB; r += 8) {
            float4 v[8];
#pragma unroll
            for (int i = 0; i < 8; ++i)
                v[i] = __ldcs(mk4 + (size_t)(r + i) * D4);
#pragma unroll
            for (int i = 0; i < 8; ++i) {
                float kr = sk[r + i];
                ad.x += kr * v[i].x; ad.y += kr * v[i].y;
                ad.z += kr * v[i].z; ad.w += kr * v[i].w;
                as.x += v[i].x * v[i].x; as.y += v[i].y * v[i].y;
                as.z += v[i].z * v[i].z; as.w += v[i].w * v[i].w;
            }
        }

        ((float4*)g_part_dot[rs])[col4] = ad;
        ((float4*)g_part_sq [rs])[col4] = as;
    }

    __syncthreads();
    __threadfence();
    if (tid == 0) atomicAdd(&g_arr1, 1u);
#if __CUDA_ARCH__ >= 900
    cudaTriggerProgrammaticLaunchCompletion();
#endif

    if (bid >= 64) return;   // colred-only blocks are done

    // ================= epilogue blocks 0..63 =================
    if (tid == 0) {
        while (atomicAdd(&g_arr1, 0u) < (unsigned)NBLK1) __nanosleep(64);
    }
    __syncthreads();
    __threadfence();

    __shared__ float sred[4];
    __shared__ float s_sum;
    __shared__ float shalf_d[128];
    __shared__ float shalf_s[128];

    // ---- slab reduction with 256 threads (two half-slab partials per j) ----
    const int jl   = tid & 127;
    const int half = tid >> 7;
    const int j    = bid * 128 + jl;
    {
        float sd = 0.f, ss = 0.f;
        const int s0 = half * 32;
#pragma unroll
        for (int s = 0; s < 32; ++s) {
            sd += g_part_dot[s0 + s][j];
            ss += g_part_sq [s0 + s][j];
        }
        if (half == 1) { shalf_d[jl] = sd; shalf_s[jl] = ss; }
        __syncthreads();
        if (half == 0) { shalf_d[jl] += sd; shalf_s[jl] += ss; }
    }
    __syncthreads();

    float ev = 0.f;
    if (tid < 128) {
        const float sd = shalf_d[jl];
        const float ss = shalf_s[jl];
        ev = __expf(sd / (g_knorm * sqrtf(ss)));
        float v = warp_sum(ev);
        if (lane == 0) sred[wid] = v;
    }
    __syncthreads();
    if (tid == 0) {
        g_evsum[bid] = (sred[0] + sred[1]) + (sred[2] + sred[3]);
        __threadfence();
        atomicAdd(&g_arr2, 1u);
    }

    if (tid == 0) {
        while (atomicAdd(&g_arr2, 0u) < 64u) __nanosleep(64);
    }
    __syncthreads();
    __threadfence();

    // ---- softmax denominator (same deterministic order as R9-R13) ----
    if (tid < 32) {
        float t = g_evsum[tid] + g_evsum[tid + 32];
        t = warp_sum(t);
        if (tid == 0) s_sum = t;
    }
    __syncthreads();

    const float inv_sum = 1.f / s_sum;
    const float beta    = 1.f / (1.f + __expf(-beta_p[0]));
    const int   minidx  = g_min_idx;

    if (tid < 128) {
        const float wr     = ev * inv_sum;
        const float wu_new = GAMMA * w_u[j] + wr + w_w[j];
        const float ww_new = beta * wr + (1.f - beta) * w_lu[j];

        out[OFF_WU + j] = wu_new;
        out[OFF_WW + j] = ww_new;
        g_addk[j] = wu_new * kvec[j];
        g_addu[j] = ww_new * uvec[j];
        g_wr[j]   = (j == minidx) ? 0.f : wr;

        float v = warp_min(wu_new);
        if (lane == 0) sred[wid] = v;
    }
    __syncthreads();
    if (tid == 0) {
        g_minpart[bid] = fminf(fminf(sred[0], sred[1]), fminf(sred[2], sred[3]));
        __threadfence();
        unsigned d = atomicAdd(&g_dep, 1u);
        if (d == 63u) {
            atomicExch(&g_arr1, 0u);
            atomicExch(&g_arr2, 0u);
            atomicExch(&g_dep,  0u);
        }
    }
}

// ---------------- kernel 3+4 fused + w_lu finisher (PDL secondary) ----------
// EXACT Round-13 body: gridsync first, NO prefetch. FROZEN.
__global__ __launch_bounds__(256) void k34_stream(const float* __restrict__ mk,
                                                  const float* __restrict__ mu,
                                                  float* __restrict__ out)
{
#if __CUDA_ARCH__ >= 900
    cudaGridDependencySynchronize();
#endif

    const int tid  = threadIdx.x;
    const int lane = tid & 31;
    const int wid  = tid >> 5;

    if (blockIdx.x == 2048) {
        // ---- w_lu_new finisher ----
        __shared__ float s_min;
        if (tid < 32) {
            float t = fminf(g_minpart[tid], g_minpart[tid + 32]);
            t = warp_min(t);
            if (tid == 0) s_min = t;
        }
        __syncthreads();
        const float minv = s_min;
#pragma unroll 8
        for (int p = 0; p < 32; ++p) {
            int j = tid + p * 256;
            out[OFF_WLU + j] = (out[OFF_WU + j] < minv) ? 1.f : 0.f;
        }
        return;
    }

    const int m   = g_min_idx;
    const int m4  = m >> 2;
    const int ml  = m & 3;

    if (blockIdx.x < 1024) {
        // ---------------- mk path ----------------
        const int row = blockIdx.x * 8 + wid;
        const float4* __restrict__ src = (const float4*)mk + (size_t)row * D4;
        float4* __restrict__ dst = (float4*)(out + OFF_MK) + (size_t)row * D4;
        const float4* __restrict__ wr4 = (const float4*)g_wr;
        const float4* __restrict__ ak4 = (const float4*)g_addk;

        float acc = 0.f;
#pragma unroll 8
        for (int it = 0; it < 64; ++it) {
            const int f = lane + (it << 5);
            float4 v = src[f];
            float4 w = __ldg(wr4 + f);
            float4 a = __ldg(ak4 + f);
            acc += w.x * v.x + w.y * v.y + w.z * v.z + w.w * v.w;
            float4 o = make_float4(v.x + a.x, v.y + a.y, v.z + a.z, v.w + a.w);
            if (f == m4) {
                if      (ml == 0) o.x = a.x;
                else if (ml == 1) o.y = a.y;
                else if (ml == 2) o.z = a.z;
                else              o.w = a.w;
            }
            dst[f] = o;
        }
        acc = warp_sum(acc);
        if (lane == 0) out[OFF_UF + row] = acc;
    } else {
        // ---------------- mu path ----------------
        const int row = (blockIdx.x - 1024) * 8 + wid;
        const float4* __restrict__ src = (const float4*)mu + (size_t)row * D4;
        float4* __restrict__ dst = (float4*)(out + OFF_MU) + (size_t)row * D4;
        const float4* __restrict__ au4 = (const float4*)g_addu;

#pragma unroll 8
        for (int it = 0; it < 64; ++it) {
            const int f = lane + (it << 5);
            float4 v = src[f];
            float4 a = __ldg(au4 + f);
            float4 o = make_float4(v.x + a.x, v.y + a.y, v.z + a.z, v.w + a.w);
            if (f == m4) {
                if      (ml == 0) o.x = a.x;
                else if (ml == 1) o.y = a.y;
                else if (ml == 2) o.z = a.z;
                else              o.w = a.w;
            }
            dst[f] = o;
        }
    }
}

// ---------------- launch ----------------
extern "C" void kernel_launch(void* const* d_in, const int* in_sizes, int n_in,
                              void* d_out, int out_size)
{
    const float* k_in   = (const float*)d_in[0];
    const float* u_in   = (const float*)d_in[1];
    const float* mk_in  = (const float*)d_in[2];
    const float* mu_in  = (const float*)d_in[3];
    const float* ww_in  = (const float*)d_in[4];
    const float* wu_in  = (const float*)d_in[5];
    const float* wlu_in = (const float*)d_in[6];
    const float* beta_in= (const float*)d_in[7];
    float* out = (float*)d_out;

    k1_fused<<<NBLK1, 256>>>(mk_in, k_in, wu_in, u_in, ww_in, wlu_in, beta_in, out);

    // PDL launch of k34: scheduled at the early trigger; gridsync gates
    // data consumption. No prefetch (R14 regression).
    cudaLaunchConfig_t cfg = {};
    cfg.gridDim  = dim3(2049, 1, 1);
    cfg.blockDim = dim3(256, 1, 1);
    cfg.dynamicSmemBytes = 0;
    cfg.stream = 0;
    cudaLaunchAttribute attrs[1];
    attrs[0].id = cudaLaunchAttributeProgrammaticStreamSerialization;
    attrs[0].val.programmaticStreamSerializationAllowed = 1;
    cfg.attrs = attrs;
    cfg.numAttrs = 1;
    cudaLaunchKernelEx(&cfg, k34_stream, mk_in, mu_in, out);
}